// round 3
// baseline (speedup 1.0000x reference)
#include <cuda_runtime.h>

// ChamferLoss: f[4,8192,3], f_[4,8192,3] -> scalar
// For each point in src, min squared distance to all dst points (both directions),
// clamped at 0, mean over points, sum of the two direction-means per batch,
// mean over batch. Equivalent to (sum of all 65536 clamped mins) / 32768.

namespace {
constexpr int kB = 4;
constexpr int kN = 8192;
constexpr int kThreads = 256;
constexpr int kSrcPerThread = 2;
constexpr int kSrcPerBlock = kThreads * kSrcPerThread;  // 512
constexpr int kChunks = kN / kSrcPerBlock;              // 16
constexpr int kBlocks = kChunks * kB * 2;               // 128
constexpr int kTile = 2048;                             // dst points per smem tile (32KB)
constexpr int kTiles = kN / kTile;                      // 4
}  // namespace

__device__ float g_partials[kBlocks];

__global__ void __launch_bounds__(kThreads, 1)
chamfer_dir_kernel(const float* __restrict__ f, const float* __restrict__ f_) {
    __shared__ float4 sdst[kTile];
    __shared__ float swsum[kThreads / 32];

    const int dir = blockIdx.z;
    const int b = blockIdx.y;
    const int chunk = blockIdx.x;

    const float* src = (dir == 0) ? f : f_;
    const float* dst = (dir == 0) ? f_ : f;
    src += (size_t)b * kN * 3;
    dst += (size_t)b * kN * 3;

    const int tid = threadIdx.x;

    // Load this thread's source points + precompute s^2.
    float sx[kSrcPerThread], sy[kSrcPerThread], sz[kSrcPerThread];
    float s2[kSrcPerThread], m[kSrcPerThread];
#pragma unroll
    for (int i = 0; i < kSrcPerThread; ++i) {
        const int n = chunk * kSrcPerBlock + i * kThreads + tid;
        const float x = src[n * 3 + 0];
        const float y = src[n * 3 + 1];
        const float z = src[n * 3 + 2];
        sx[i] = x; sy[i] = y; sz[i] = z;
        s2[i] = fmaf(z, z, fmaf(y, y, x * x));
        m[i] = 3.4e38f;
    }

    // Loop over dst tiles resident in shared memory.
    for (int t = 0; t < kTiles; ++t) {
        const float* dt = dst + (size_t)t * kTile * 3;
        for (int j = tid; j < kTile; j += kThreads) {
            const float x = dt[j * 3 + 0];
            const float y = dt[j * 3 + 1];
            const float z = dt[j * 3 + 2];
            sdst[j] = make_float4(x, y, z, fmaf(z, z, fmaf(y, y, x * x)));
        }
        __syncthreads();

#pragma unroll 8
        for (int j = 0; j < kTile; ++j) {
            const float4 p = sdst[j];  // broadcast across the warp, conflict-free
#pragma unroll
            for (int i = 0; i < kSrcPerThread; ++i) {
                // cross = p . s   (3 FFMA on fma pipe)
                const float c = fmaf(p.z, sz[i], fmaf(p.y, sy[i], p.x * sx[i]));
                // t = d^2 - 2*cross   (FFMA with immediate multiplier, rt=1)
                const float tv = fmaf(-2.0f, c, p.w);
                m[i] = fminf(m[i], tv);  // alu pipe
            }
        }
        __syncthreads();
    }

    // res = max(s^2 + min_t, 0); sum the thread's src points.
    float v = 0.0f;
#pragma unroll
    for (int i = 0; i < kSrcPerThread; ++i) {
        v += fmaxf(s2[i] + m[i], 0.0f);
    }

    // Warp reduce then block reduce (deterministic per-block partial).
#pragma unroll
    for (int off = 16; off > 0; off >>= 1) {
        v += __shfl_xor_sync(0xffffffffu, v, off);
    }
    const int lane = tid & 31;
    const int wid = tid >> 5;
    if (lane == 0) swsum[wid] = v;
    __syncthreads();
    if (tid == 0) {
        float s = 0.0f;
#pragma unroll
        for (int w = 0; w < kThreads / 32; ++w) s += swsum[w];
        g_partials[chunk + kChunks * (b + kB * dir)] = s;
    }
}

__global__ void chamfer_finalize_kernel(float* __restrict__ out) {
    if (threadIdx.x == 0) {
        float s = 0.0f;
        for (int i = 0; i < kBlocks; ++i) s += g_partials[i];
        out[0] = s / (float)(kN * kB);  // / 32768
    }
}

extern "C" void kernel_launch(void* const* d_in, const int* in_sizes, int n_in,
                              void* d_out, int out_size) {
    const float* f = (const float*)d_in[0];
    const float* f_ = (const float*)d_in[1];
    (void)in_sizes; (void)n_in; (void)out_size;

    dim3 grid(kChunks, kB, 2);
    chamfer_dir_kernel<<<grid, kThreads>>>(f, f_);
    chamfer_finalize_kernel<<<1, 32>>>((float*)d_out);
}

// round 4
// speedup vs baseline: 1.3279x; 1.3279x over previous
#include <cuda_runtime.h>

// ChamferLoss: f[4,8192,3], f_[4,8192,3] -> scalar.
// d(s,p) = ||s||^2 + ||p||^2 - 2 s.p ; clamp >=0 ; min over dst per src point,
// both directions; sum(all mins)/32768.
//
// R4: packed fp32 math (fma.rn.f32x2). Two dst points packed per 64-bit lane
// operand; src replicas (sx,sx) are loop-invariant packs. Tile is pre-paired
// in smem so inner loop needs no pack/unpack MOVs for dst.

namespace {
constexpr int kB = 4;
constexpr int kN = 8192;
constexpr int kThreads = 256;
constexpr int kSrcPerThread = 2;
constexpr int kSrcPerBlock = kThreads * kSrcPerThread;  // 512
constexpr int kChunks = kN / kSrcPerBlock;              // 16
constexpr int kBlocks = kChunks * kB * 2;               // 128
constexpr int kTile = 2048;                             // dst points per smem tile
constexpr int kPairs = kTile / 2;                       // 1024 packed dst pairs
constexpr int kTiles = kN / kTile;                      // 4
}  // namespace

__device__ float g_partials[kBlocks];

__device__ __forceinline__ unsigned long long pack2(float lo, float hi) {
    unsigned long long r;
    asm("mov.b64 %0, {%1, %2};" : "=l"(r) : "f"(lo), "f"(hi));
    return r;
}
__device__ __forceinline__ void unpack2(unsigned long long v, float& lo, float& hi) {
    asm("mov.b64 {%0, %1}, %2;" : "=f"(lo), "=f"(hi) : "l"(v));
}
__device__ __forceinline__ unsigned long long mul2(unsigned long long a, unsigned long long b) {
    unsigned long long d;
    asm("mul.rn.f32x2 %0, %1, %2;" : "=l"(d) : "l"(a), "l"(b));
    return d;
}
__device__ __forceinline__ unsigned long long fma2(unsigned long long a, unsigned long long b,
                                                   unsigned long long c) {
    unsigned long long d;
    asm("fma.rn.f32x2 %0, %1, %2, %3;" : "=l"(d) : "l"(a), "l"(b), "l"(c));
    return d;
}

__global__ void __launch_bounds__(kThreads, 1)
chamfer_dir_kernel(const float* __restrict__ f, const float* __restrict__ f_) {
    // Paired dst tile: sA[jp] = {pack(x0,x1), pack(y0,y1)},
    //                  sB[jp] = {pack(z0,z1), pack(w0,w1)}   (w = ||p||^2)
    __shared__ ulonglong2 sA[kPairs];
    __shared__ ulonglong2 sB[kPairs];
    __shared__ float swsum[kThreads / 32];

    const int dir = blockIdx.z;
    const int b = blockIdx.y;
    const int chunk = blockIdx.x;

    const float* src = (dir == 0) ? f : f_;
    const float* dst = (dir == 0) ? f_ : f;
    src += (size_t)b * kN * 3;
    dst += (size_t)b * kN * 3;

    const int tid = threadIdx.x;

    // Load this thread's src points; build loop-invariant replicated packs.
    unsigned long long sxx[kSrcPerThread], syy[kSrcPerThread], szz[kSrcPerThread];
    float s2[kSrcPerThread];
    float m0[kSrcPerThread], m1[kSrcPerThread];  // mins over even / odd dst
#pragma unroll
    for (int i = 0; i < kSrcPerThread; ++i) {
        const int n = chunk * kSrcPerBlock + i * kThreads + tid;
        const float x = src[n * 3 + 0];
        const float y = src[n * 3 + 1];
        const float z = src[n * 3 + 2];
        sxx[i] = pack2(x, x);
        syy[i] = pack2(y, y);
        szz[i] = pack2(z, z);
        s2[i] = fmaf(z, z, fmaf(y, y, x * x));
        m0[i] = 3.4e38f;
        m1[i] = 3.4e38f;
    }
    const unsigned long long neg2 = pack2(-2.0f, -2.0f);

    for (int t = 0; t < kTiles; ++t) {
        const float* dt = dst + (size_t)t * kTile * 3;
        for (int jp = tid; jp < kPairs; jp += kThreads) {
            const float x0 = dt[jp * 6 + 0];
            const float y0 = dt[jp * 6 + 1];
            const float z0 = dt[jp * 6 + 2];
            const float x1 = dt[jp * 6 + 3];
            const float y1 = dt[jp * 6 + 4];
            const float z1 = dt[jp * 6 + 5];
            const float w0 = fmaf(z0, z0, fmaf(y0, y0, x0 * x0));
            const float w1 = fmaf(z1, z1, fmaf(y1, y1, x1 * x1));
            sA[jp] = make_ulonglong2(pack2(x0, x1), pack2(y0, y1));
            sB[jp] = make_ulonglong2(pack2(z0, z1), pack2(w0, w1));
        }
        __syncthreads();

#pragma unroll 8
        for (int jp = 0; jp < kPairs; ++jp) {
            const ulonglong2 A = sA[jp];  // broadcast LDS.128, conflict-free
            const ulonglong2 B = sB[jp];
#pragma unroll
            for (int i = 0; i < kSrcPerThread; ++i) {
                unsigned long long c = mul2(A.x, sxx[i]);
                c = fma2(A.y, syy[i], c);
                c = fma2(B.x, szz[i], c);
                const unsigned long long tv = fma2(c, neg2, B.y);  // w - 2*cross
                float t0, t1;
                unpack2(tv, t0, t1);
                m0[i] = fminf(m0[i], t0);
                m1[i] = fminf(m1[i], t1);
            }
        }
        __syncthreads();
    }

    float v = 0.0f;
#pragma unroll
    for (int i = 0; i < kSrcPerThread; ++i) {
        const float mi = fminf(m0[i], m1[i]);
        v += fmaxf(s2[i] + mi, 0.0f);
    }

#pragma unroll
    for (int off = 16; off > 0; off >>= 1) {
        v += __shfl_xor_sync(0xffffffffu, v, off);
    }
    const int lane = tid & 31;
    const int wid = tid >> 5;
    if (lane == 0) swsum[wid] = v;
    __syncthreads();
    if (tid == 0) {
        float s = 0.0f;
#pragma unroll
        for (int w = 0; w < kThreads / 32; ++w) s += swsum[w];
        g_partials[chunk + kChunks * (b + kB * dir)] = s;
    }
}

__global__ void chamfer_finalize_kernel(float* __restrict__ out) {
    if (threadIdx.x == 0) {
        float s = 0.0f;
        for (int i = 0; i < kBlocks; ++i) s += g_partials[i];
        out[0] = s / (float)(kN * kB);  // / 32768
    }
}

extern "C" void kernel_launch(void* const* d_in, const int* in_sizes, int n_in,
                              void* d_out, int out_size) {
    const float* f = (const float*)d_in[0];
    const float* f_ = (const float*)d_in[1];
    (void)in_sizes; (void)n_in; (void)out_size;

    dim3 grid(kChunks, kB, 2);
    chamfer_dir_kernel<<<grid, kThreads>>>(f, f_);
    chamfer_finalize_kernel<<<1, 32>>>((float*)d_out);
}